// round 2
// baseline (speedup 1.0000x reference)
#include <cuda_runtime.h>

#define NN 50000
#define NE 800000
#define D  128
#define BM 128      // node rows per transform block
#define BK 16       // k-chunk

// Scratch (device globals — no allocation allowed)
__device__ float g_y[NN * D];        // transformed features y = x @ W^T
__device__ int   g_hist[NN];         // per-row edge counts
__device__ int   g_off[NN];          // CSR row starts
__device__ int   g_cursor[NN];       // fill cursors for reorder
__device__ int   g_scol[NE];         // sorted edge cols
__device__ float g_sw[NE];           // sorted edge weights

// ---------------------------------------------------------------------------
// Kernel 1: y = x @ W^T  (W is [D_OUT, D_IN] row-major)
// 128x128 tile, BK=16, 256 threads, 8x8 micro-tile in 4+4 split layout.
// ---------------------------------------------------------------------------
__global__ __launch_bounds__(256) void transform_kernel(
    const float* __restrict__ x, const float* __restrict__ W)
{
    __shared__ float xs[BK][BM + 4];   // [k][node_row]   (transposed)
    __shared__ float ws[BK][D  + 4];   // [k][out_col]    (transposed)

    const int t   = threadIdx.x;
    const int row0 = blockIdx.x * BM;
    const int tx  = (t & 15) * 4;      // col group base (0..60)
    const int ty  = (t >> 4) * 4;      // row group base (0..60)

    float acc[8][8];
#pragma unroll
    for (int i = 0; i < 8; i++)
#pragma unroll
        for (int j = 0; j < 8; j++) acc[i][j] = 0.f;

#pragma unroll 1
    for (int kc = 0; kc < D; kc += BK) {
        __syncthreads();
        // W chunk transposed: ws[k][col] = W[col][kc+k].  D*BK = 2048 floats.
#pragma unroll
        for (int i = t * 4; i < D * BK; i += 256 * 4) {
            int col = i / BK;
            int kk  = i % BK;
            float4 v = *reinterpret_cast<const float4*>(&W[col * D + kc + kk]);
            ws[kk + 0][col] = v.x;
            ws[kk + 1][col] = v.y;
            ws[kk + 2][col] = v.z;
            ws[kk + 3][col] = v.w;
        }
        // x chunk transposed: xs[k][r] = x[row0+r][kc+k].  BM*BK = 2048 floats.
#pragma unroll
        for (int i = t * 4; i < BM * BK; i += 256 * 4) {
            int r  = i / BK;
            int kk = i % BK;
            float4 v = make_float4(0.f, 0.f, 0.f, 0.f);
            if (row0 + r < NN)
                v = *reinterpret_cast<const float4*>(&x[(row0 + r) * D + kc + kk]);
            xs[kk + 0][r] = v.x;
            xs[kk + 1][r] = v.y;
            xs[kk + 2][r] = v.z;
            xs[kk + 3][r] = v.w;
        }
        __syncthreads();

#pragma unroll
        for (int k = 0; k < BK; k++) {
            float4 a0 = *reinterpret_cast<const float4*>(&xs[k][ty]);
            float4 a1 = *reinterpret_cast<const float4*>(&xs[k][ty + 64]);
            float4 b0 = *reinterpret_cast<const float4*>(&ws[k][tx]);
            float4 b1 = *reinterpret_cast<const float4*>(&ws[k][tx + 64]);
            float xv[8] = {a0.x, a0.y, a0.z, a0.w, a1.x, a1.y, a1.z, a1.w};
            float wv[8] = {b0.x, b0.y, b0.z, b0.w, b1.x, b1.y, b1.z, b1.w};
#pragma unroll
            for (int i = 0; i < 8; i++)
#pragma unroll
                for (int j = 0; j < 8; j++)
                    acc[i][j] += xv[i] * wv[j];
        }
    }

    // Epilogue: rows {row0+ty+i, row0+64+ty+i}, cols {tx+j, 64+tx+j}
#pragma unroll
    for (int i = 0; i < 8; i++) {
        int r = row0 + (i < 4 ? ty + i : 64 + ty + (i - 4));
        if (r < NN) {
            float4 v0 = make_float4(acc[i][0], acc[i][1], acc[i][2], acc[i][3]);
            float4 v1 = make_float4(acc[i][4], acc[i][5], acc[i][6], acc[i][7]);
            *reinterpret_cast<float4*>(&g_y[r * D + tx])      = v0;
            *reinterpret_cast<float4*>(&g_y[r * D + 64 + tx]) = v1;
        }
    }
}

// ---------------------------------------------------------------------------
// CSR construction (must re-run every launch; graph replays all kernels)
// ---------------------------------------------------------------------------
__global__ void zero_hist_kernel()
{
    int i = blockIdx.x * blockDim.x + threadIdx.x;
    if (i < NN) g_hist[i] = 0;
}

__global__ void count_kernel(const int* __restrict__ erow)
{
    int e = blockIdx.x * blockDim.x + threadIdx.x;
    if (e < NE) atomicAdd(&g_hist[erow[e]], 1);
}

// Single-block exclusive scan of g_hist -> g_off, g_cursor. 1024 threads.
__global__ __launch_bounds__(1024) void scan_kernel()
{
    __shared__ int psum[1024];
    const int t = threadIdx.x;
    const int CH = (NN + 1023) / 1024;   // 49
    const int lo = t * CH;
    const int hi = min(lo + CH, NN);

    int s = 0;
    for (int i = lo; i < hi; i++) s += g_hist[i];
    psum[t] = s;
    __syncthreads();

    // Hillis-Steele inclusive scan over 1024 partials
    for (int d = 1; d < 1024; d <<= 1) {
        int v = (t >= d) ? psum[t - d] : 0;
        __syncthreads();
        psum[t] += v;
        __syncthreads();
    }
    int off = (t == 0) ? 0 : psum[t - 1];  // exclusive prefix
    for (int i = lo; i < hi; i++) {
        g_off[i]    = off;
        g_cursor[i] = off;
        off += g_hist[i];
    }
}

__global__ void reorder_kernel(const int* __restrict__ erow,
                               const int* __restrict__ ecol,
                               const float* __restrict__ ew)
{
    int e = blockIdx.x * blockDim.x + threadIdx.x;
    if (e >= NE) return;
    int r   = erow[e];
    int pos = atomicAdd(&g_cursor[r], 1);
    g_scol[pos] = ecol[e];
    g_sw[pos]   = ew[e];
}

// ---------------------------------------------------------------------------
// Kernel 5: gather-side reduction. One warp per node.
// out[i] = b + sum_j w_j * y[col_j]   (lane owns float4 of the 128-d row)
// ---------------------------------------------------------------------------
__global__ __launch_bounds__(256) void gather_kernel(
    float* __restrict__ out, const float* __restrict__ b)
{
    const int warp = (blockIdx.x * blockDim.x + threadIdx.x) >> 5;
    const int lane = threadIdx.x & 31;
    if (warp >= NN) return;

    const int start = g_off[warp];
    const int deg   = g_hist[warp];
    const int end   = start + deg;

    const float4* y4 = reinterpret_cast<const float4*>(g_y);

    float4 acc = *reinterpret_cast<const float4*>(&b[lane * 4]);

    for (int base = start; base < end; base += 32) {
        int n = min(32, end - base);
        int   c = 0;
        float w = 0.f;
        if (lane < n) {
            c = g_scol[base + lane];
            w = g_sw[base + lane];
        }
#pragma unroll 4
        for (int jj = 0; jj < n; jj++) {
            int   cc = __shfl_sync(0xffffffffu, c, jj);
            float ww = __shfl_sync(0xffffffffu, w, jj);
            float4 v = y4[cc * 32 + lane];
            acc.x += ww * v.x;
            acc.y += ww * v.y;
            acc.z += ww * v.z;
            acc.w += ww * v.w;
        }
    }

    reinterpret_cast<float4*>(out)[warp * 32 + lane] = acc;
}

// ---------------------------------------------------------------------------
extern "C" void kernel_launch(void* const* d_in, const int* in_sizes, int n_in,
                              void* d_out, int out_size)
{
    const float* x    = (const float*)d_in[0];
    const int*   erow = (const int*)  d_in[1];
    const int*   ecol = (const int*)  d_in[2];
    const float* ew   = (const float*)d_in[3];
    const float* W    = (const float*)d_in[4];
    const float* b    = (const float*)d_in[5];
    float*       out  = (float*)d_out;

    zero_hist_kernel<<<(NN + 255) / 256, 256>>>();
    count_kernel<<<(NE + 255) / 256, 256>>>(erow);
    transform_kernel<<<(NN + BM - 1) / BM, 256>>>(x, W);   // overlaps L2 use of count
    scan_kernel<<<1, 1024>>>();
    reorder_kernel<<<(NE + 255) / 256, 256>>>(erow, ecol, ew);
    gather_kernel<<<(NN * 32 + 255) / 256, 256>>>(out, b);
}

// round 3
// speedup vs baseline: 1.7154x; 1.7154x over previous
#include <cuda_runtime.h>

#define NN 50000
#define NE 800000
#define D  128
#define BM 128
#define BK 16

#define SCAN_BLK 256
#define SCAN_NB  ((NN + SCAN_BLK - 1) / SCAN_BLK)   // 196

// Scratch (device globals — no allocation allowed)
__device__ float g_y[NN * D];      // y = x @ W^T
__device__ int   g_hist[NN];       // per-row edge counts
__device__ int   g_off[NN];        // CSR row starts
__device__ int   g_cursor[NN];     // fill cursors
__device__ int2  g_edge[NE];       // sorted (col, weight-bits)
__device__ int   g_bsum[SCAN_NB];  // per-block partial sums
__device__ int   g_bpre[SCAN_NB];  // exclusive block prefixes

// ---------------------------------------------------------------------------
// Kernel 1: y = x @ W^T   (128x128 tile, BK=16, 256 thr, 8x8 micro-tile)
// ---------------------------------------------------------------------------
__global__ __launch_bounds__(256) void transform_kernel(
    const float* __restrict__ x, const float* __restrict__ W)
{
    __shared__ float xs[BK][BM + 4];
    __shared__ float ws[BK][D  + 4];

    const int t    = threadIdx.x;
    const int row0 = blockIdx.x * BM;
    const int tx   = (t & 15) * 4;
    const int ty   = (t >> 4) * 4;

    float acc[8][8];
#pragma unroll
    for (int i = 0; i < 8; i++)
#pragma unroll
        for (int j = 0; j < 8; j++) acc[i][j] = 0.f;

#pragma unroll 1
    for (int kc = 0; kc < D; kc += BK) {
        __syncthreads();
#pragma unroll
        for (int i = t * 4; i < D * BK; i += 256 * 4) {
            int col = i / BK, kk = i % BK;
            float4 v = *reinterpret_cast<const float4*>(&W[col * D + kc + kk]);
            ws[kk + 0][col] = v.x; ws[kk + 1][col] = v.y;
            ws[kk + 2][col] = v.z; ws[kk + 3][col] = v.w;
        }
#pragma unroll
        for (int i = t * 4; i < BM * BK; i += 256 * 4) {
            int r = i / BK, kk = i % BK;
            float4 v = make_float4(0.f, 0.f, 0.f, 0.f);
            if (row0 + r < NN)
                v = *reinterpret_cast<const float4*>(&x[(row0 + r) * D + kc + kk]);
            xs[kk + 0][r] = v.x; xs[kk + 1][r] = v.y;
            xs[kk + 2][r] = v.z; xs[kk + 3][r] = v.w;
        }
        __syncthreads();

#pragma unroll
        for (int k = 0; k < BK; k++) {
            float4 a0 = *reinterpret_cast<const float4*>(&xs[k][ty]);
            float4 a1 = *reinterpret_cast<const float4*>(&xs[k][ty + 64]);
            float4 b0 = *reinterpret_cast<const float4*>(&ws[k][tx]);
            float4 b1 = *reinterpret_cast<const float4*>(&ws[k][tx + 64]);
            float xv[8] = {a0.x, a0.y, a0.z, a0.w, a1.x, a1.y, a1.z, a1.w};
            float wv[8] = {b0.x, b0.y, b0.z, b0.w, b1.x, b1.y, b1.z, b1.w};
#pragma unroll
            for (int i = 0; i < 8; i++)
#pragma unroll
                for (int j = 0; j < 8; j++)
                    acc[i][j] += xv[i] * wv[j];
        }
    }

#pragma unroll
    for (int i = 0; i < 8; i++) {
        int r = row0 + (i < 4 ? ty + i : 64 + ty + (i - 4));
        if (r < NN) {
            float4 v0 = make_float4(acc[i][0], acc[i][1], acc[i][2], acc[i][3]);
            float4 v1 = make_float4(acc[i][4], acc[i][5], acc[i][6], acc[i][7]);
            *reinterpret_cast<float4*>(&g_y[r * D + tx])      = v0;
            *reinterpret_cast<float4*>(&g_y[r * D + 64 + tx]) = v1;
        }
    }
}

// ---------------------------------------------------------------------------
// CSR construction
// ---------------------------------------------------------------------------
__global__ void zero_hist_kernel()
{
    int i = blockIdx.x * blockDim.x + threadIdx.x;
    if (i < NN) g_hist[i] = 0;
}

__global__ void count_kernel(const int* __restrict__ erow)
{
    int e = blockIdx.x * blockDim.x + threadIdx.x;
    if (e < NE) atomicAdd(&g_hist[erow[e]], 1);
}

// Phase 1: per-block sums of g_hist (256 elems/block)
__global__ __launch_bounds__(SCAN_BLK) void scan_partials_kernel()
{
    __shared__ int wsum[SCAN_BLK / 32];
    int i = blockIdx.x * SCAN_BLK + threadIdx.x;
    int v = (i < NN) ? g_hist[i] : 0;
#pragma unroll
    for (int d = 16; d > 0; d >>= 1) v += __shfl_down_sync(0xffffffffu, v, d);
    if ((threadIdx.x & 31) == 0) wsum[threadIdx.x >> 5] = v;
    __syncthreads();
    if (threadIdx.x < SCAN_BLK / 32) {
        int s = wsum[threadIdx.x];
#pragma unroll
        for (int d = SCAN_BLK / 64; d > 0; d >>= 1)
            s += __shfl_down_sync(0xffu, s, d);
        if (threadIdx.x == 0) g_bsum[blockIdx.x] = s;
    }
}

// Phase 2: single-block exclusive scan of SCAN_NB (=196) partials
__global__ __launch_bounds__(256) void scan_bsum_kernel()
{
    __shared__ int sh[256];
    int t = threadIdx.x;
    int v = (t < SCAN_NB) ? g_bsum[t] : 0;
    sh[t] = v;
    __syncthreads();
#pragma unroll
    for (int d = 1; d < 256; d <<= 1) {
        int u = (t >= d) ? sh[t - d] : 0;
        __syncthreads();
        sh[t] += u;
        __syncthreads();
    }
    if (t < SCAN_NB) g_bpre[t] = sh[t] - v;   // exclusive
}

// Phase 3: intra-block exclusive scan + block prefix -> g_off / g_cursor
__global__ __launch_bounds__(SCAN_BLK) void scan_final_kernel()
{
    __shared__ int wpre[SCAN_BLK / 32];
    int i    = blockIdx.x * SCAN_BLK + threadIdx.x;
    int lane = threadIdx.x & 31;
    int wid  = threadIdx.x >> 5;
    int v    = (i < NN) ? g_hist[i] : 0;

    // inclusive warp scan
    int inc = v;
#pragma unroll
    for (int d = 1; d < 32; d <<= 1) {
        int u = __shfl_up_sync(0xffffffffu, inc, d);
        if (lane >= d) inc += u;
    }
    if (lane == 31) wpre[wid] = inc;
    __syncthreads();
    if (threadIdx.x < SCAN_BLK / 32) {
        // inclusive scan of 8 warp sums in warp 0
        int s = wpre[threadIdx.x];
#pragma unroll
        for (int d = 1; d < SCAN_BLK / 32; d <<= 1) {
            int u = __shfl_up_sync(0xffu, s, d);
            if ((int)threadIdx.x >= d) s += u;
        }
        wpre[threadIdx.x] = s;
    }
    __syncthreads();

    int warp_prefix = (wid == 0) ? 0 : wpre[wid - 1];
    int exc = g_bpre[blockIdx.x] + warp_prefix + (inc - v);
    if (i < NN) {
        g_off[i]    = exc;
        g_cursor[i] = exc;
    }
}

__global__ void reorder_kernel(const int* __restrict__ erow,
                               const int* __restrict__ ecol,
                               const float* __restrict__ ew)
{
    int e = blockIdx.x * blockDim.x + threadIdx.x;
    if (e >= NE) return;
    int r   = erow[e];
    int pos = atomicAdd(&g_cursor[r], 1);
    g_edge[pos] = make_int2(ecol[e], __float_as_int(ew[e]));
}

// ---------------------------------------------------------------------------
// Gather-side reduction: one warp per node.
// ---------------------------------------------------------------------------
__global__ __launch_bounds__(256) void gather_kernel(
    float* __restrict__ out, const float* __restrict__ b)
{
    const int warp = (blockIdx.x * blockDim.x + threadIdx.x) >> 5;
    const int lane = threadIdx.x & 31;
    if (warp >= NN) return;

    const int start = g_off[warp];
    const int end   = start + g_hist[warp];

    const float4* y4 = reinterpret_cast<const float4*>(g_y);
    float4 acc = *reinterpret_cast<const float4*>(&b[lane * 4]);

    for (int base = start; base < end; base += 32) {
        int n = min(32, end - base);
        int2 e = make_int2(0, 0);
        if (lane < n) e = g_edge[base + lane];
#pragma unroll 4
        for (int jj = 0; jj < n; jj++) {
            int   cc = __shfl_sync(0xffffffffu, e.x, jj);
            float ww = __int_as_float(__shfl_sync(0xffffffffu, e.y, jj));
            float4 v = y4[cc * 32 + lane];
            acc.x += ww * v.x;
            acc.y += ww * v.y;
            acc.z += ww * v.z;
            acc.w += ww * v.w;
        }
    }

    reinterpret_cast<float4*>(out)[warp * 32 + lane] = acc;
}

// ---------------------------------------------------------------------------
extern "C" void kernel_launch(void* const* d_in, const int* in_sizes, int n_in,
                              void* d_out, int out_size)
{
    const float* x    = (const float*)d_in[0];
    const int*   erow = (const int*)  d_in[1];
    const int*   ecol = (const int*)  d_in[2];
    const float* ew   = (const float*)d_in[3];
    const float* W    = (const float*)d_in[4];
    const float* b    = (const float*)d_in[5];
    float*       out  = (float*)d_out;

    zero_hist_kernel<<<(NN + 255) / 256, 256>>>();
    count_kernel<<<(NE + 255) / 256, 256>>>(erow);
    transform_kernel<<<(NN + BM - 1) / BM, 256>>>(x, W);
    scan_partials_kernel<<<SCAN_NB, SCAN_BLK>>>();
    scan_bsum_kernel<<<1, 256>>>();
    scan_final_kernel<<<SCAN_NB, SCAN_BLK>>>();
    reorder_kernel<<<(NE + 255) / 256, 256>>>(erow, ecol, ew);
    gather_kernel<<<(NN * 32 + 255) / 256, 256>>>(out, b);
}

// round 5
// speedup vs baseline: 1.9899x; 1.1600x over previous
#include <cuda_runtime.h>
#include <cuda_bf16.h>
#include <cstdint>

#define NN 50000
#define NE 800000
#define D  128

#define SCAN_BLK 256
#define SCAN_NB  ((NN + SCAN_BLK - 1) / SCAN_BLK)   // 196
#define TBLK ((NN + 127) / 128)                     // 391

// Scratch (device globals — no allocation allowed)
__device__ float g_y[NN * D];
__device__ int   g_hist[NN];
__device__ int   g_off[NN];
__device__ int   g_cursor[NN];
__device__ int2  g_edge[NE];
__device__ int   g_bsum[SCAN_NB];
__device__ int   g_bpre[SCAN_NB];

// ---------------------------------------------------------------------------
// Transform: y = x @ W^T via split-bf16 mma.sync (sm_80+ HMMA path).
// CTA = 128 node rows x 128 out cols, 256 threads (8 warps).
// SMEM: 4 bf16 tiles (x_hi, x_lo, W_hi, W_lo), row stride 136 (conflict-free).
// ---------------------------------------------------------------------------
#define SP   136                      // padded row stride (bf16 elems)
#define TILE_B (128 * SP * 2)         // 34816 B per tile
#define OFF_XH 0
#define OFF_XL (1 * TILE_B)
#define OFF_WH (2 * TILE_B)
#define OFF_WL (3 * TILE_B)
#define SM_DYN (4 * TILE_B)           // 139264 B

__device__ __forceinline__ void mma_bf16(float* c, const uint32_t a[4],
                                         uint32_t b0, uint32_t b1) {
    asm volatile(
        "mma.sync.aligned.m16n8k16.row.col.f32.bf16.bf16.f32 "
        "{%0,%1,%2,%3}, {%4,%5,%6,%7}, {%8,%9}, {%0,%1,%2,%3};"
        : "+f"(c[0]), "+f"(c[1]), "+f"(c[2]), "+f"(c[3])
        : "r"(a[0]), "r"(a[1]), "r"(a[2]), "r"(a[3]), "r"(b0), "r"(b1));
}

__global__ __launch_bounds__(256) void transform_mma_kernel(
    const float* __restrict__ x, const float* __restrict__ W)
{
    extern __shared__ char smem[];
    const int tid  = threadIdx.x;
    const int wid  = tid >> 5;
    const int lane = tid & 31;
    const int row0 = blockIdx.x * 128;

    // ---- Fill: convert x block and W to split-bf16 tiles ----
#pragma unroll
    for (int i = tid * 4; i < 128 * 128; i += 256 * 4) {
        const int row = i >> 7, col = i & 127;
        const uint32_t so = (uint32_t)row * (SP * 2) + (uint32_t)col * 2;

        float4 v = make_float4(0.f, 0.f, 0.f, 0.f);
        if (row0 + row < NN)
            v = *reinterpret_cast<const float4*>(&x[(row0 + row) * D + col]);
        {
            __nv_bfloat16 h0 = __float2bfloat16(v.x), h1 = __float2bfloat16(v.y);
            __nv_bfloat16 h2 = __float2bfloat16(v.z), h3 = __float2bfloat16(v.w);
            __nv_bfloat16 l0 = __float2bfloat16(v.x - __bfloat162float(h0));
            __nv_bfloat16 l1 = __float2bfloat16(v.y - __bfloat162float(h1));
            __nv_bfloat16 l2 = __float2bfloat16(v.z - __bfloat162float(h2));
            __nv_bfloat16 l3 = __float2bfloat16(v.w - __bfloat162float(h3));
            __nv_bfloat162 h01 = {h0, h1}, h23 = {h2, h3};
            __nv_bfloat162 l01 = {l0, l1}, l23 = {l2, l3};
            *reinterpret_cast<uint32_t*>(smem + OFF_XH + so)     = *reinterpret_cast<uint32_t*>(&h01);
            *reinterpret_cast<uint32_t*>(smem + OFF_XH + so + 4) = *reinterpret_cast<uint32_t*>(&h23);
            *reinterpret_cast<uint32_t*>(smem + OFF_XL + so)     = *reinterpret_cast<uint32_t*>(&l01);
            *reinterpret_cast<uint32_t*>(smem + OFF_XL + so + 4) = *reinterpret_cast<uint32_t*>(&l23);
        }
        float4 w = *reinterpret_cast<const float4*>(&W[row * D + col]);
        {
            __nv_bfloat16 h0 = __float2bfloat16(w.x), h1 = __float2bfloat16(w.y);
            __nv_bfloat16 h2 = __float2bfloat16(w.z), h3 = __float2bfloat16(w.w);
            __nv_bfloat16 l0 = __float2bfloat16(w.x - __bfloat162float(h0));
            __nv_bfloat16 l1 = __float2bfloat16(w.y - __bfloat162float(h1));
            __nv_bfloat16 l2 = __float2bfloat16(w.z - __bfloat162float(h2));
            __nv_bfloat16 l3 = __float2bfloat16(w.w - __bfloat162float(h3));
            __nv_bfloat162 h01 = {h0, h1}, h23 = {h2, h3};
            __nv_bfloat162 l01 = {l0, l1}, l23 = {l2, l3};
            *reinterpret_cast<uint32_t*>(smem + OFF_WH + so)     = *reinterpret_cast<uint32_t*>(&h01);
            *reinterpret_cast<uint32_t*>(smem + OFF_WH + so + 4) = *reinterpret_cast<uint32_t*>(&h23);
            *reinterpret_cast<uint32_t*>(smem + OFF_WL + so)     = *reinterpret_cast<uint32_t*>(&l01);
            *reinterpret_cast<uint32_t*>(smem + OFF_WL + so + 4) = *reinterpret_cast<uint32_t*>(&l23);
        }
    }
    __syncthreads();

    // ---- MMA mainloop: warp owns rows [wid*16, wid*16+16) ----
    const int g  = lane >> 2;        // group row
    const int t2 = (lane & 3) * 2;   // k pair base
    const int mrow = wid * 16;

    float acc[16][4];
#pragma unroll
    for (int i = 0; i < 16; i++)
#pragma unroll
        for (int j = 0; j < 4; j++) acc[i][j] = 0.f;

    // byte offset helper: row r, col c -> r*272 + c*2
#define LD32(base, r, c) (*reinterpret_cast<const uint32_t*>(smem + (base) + (uint32_t)(r) * (SP * 2) + (uint32_t)(c) * 2))

#pragma unroll
    for (int kt = 0; kt < 8; kt++) {
        const int k0 = kt * 16;
        uint32_t ah[4], al[4];
        ah[0] = LD32(OFF_XH, mrow + g,     k0 + t2);
        ah[1] = LD32(OFF_XH, mrow + g + 8, k0 + t2);
        ah[2] = LD32(OFF_XH, mrow + g,     k0 + t2 + 8);
        ah[3] = LD32(OFF_XH, mrow + g + 8, k0 + t2 + 8);
        al[0] = LD32(OFF_XL, mrow + g,     k0 + t2);
        al[1] = LD32(OFF_XL, mrow + g + 8, k0 + t2);
        al[2] = LD32(OFF_XL, mrow + g,     k0 + t2 + 8);
        al[3] = LD32(OFF_XL, mrow + g + 8, k0 + t2 + 8);

#pragma unroll
        for (int nt = 0; nt < 16; nt++) {
            const int n0 = nt * 8;
            uint32_t bh0 = LD32(OFF_WH, n0 + g, k0 + t2);
            uint32_t bh1 = LD32(OFF_WH, n0 + g, k0 + t2 + 8);
            uint32_t bl0 = LD32(OFF_WL, n0 + g, k0 + t2);
            uint32_t bl1 = LD32(OFF_WL, n0 + g, k0 + t2 + 8);
            mma_bf16(acc[nt], ah, bh0, bh1);   // hi*hi
            mma_bf16(acc[nt], al, bh0, bh1);   // lo_x*hi
            mma_bf16(acc[nt], ah, bl0, bl1);   // hi*lo_w
        }
    }
#undef LD32

    // ---- Epilogue: D fragment (c0,c1)=row g cols t2,t2+1; (c2,c3)=row g+8 ----
    const int r_up = row0 + mrow + g;
    const int r_dn = r_up + 8;
#pragma unroll
    for (int nt = 0; nt < 16; nt++) {
        const int col = nt * 8 + t2;
        if (r_up < NN)
            *reinterpret_cast<float2*>(&g_y[r_up * D + col]) = make_float2(acc[nt][0], acc[nt][1]);
        if (r_dn < NN)
            *reinterpret_cast<float2*>(&g_y[r_dn * D + col]) = make_float2(acc[nt][2], acc[nt][3]);
    }
}

// ---------------------------------------------------------------------------
// CSR construction (unchanged from R3)
// ---------------------------------------------------------------------------
__global__ void zero_hist_kernel()
{
    int i = blockIdx.x * blockDim.x + threadIdx.x;
    if (i < NN) g_hist[i] = 0;
}

__global__ void count_kernel(const int* __restrict__ erow)
{
    int e = blockIdx.x * blockDim.x + threadIdx.x;
    if (e < NE) atomicAdd(&g_hist[erow[e]], 1);
}

__global__ __launch_bounds__(SCAN_BLK) void scan_partials_kernel()
{
    __shared__ int wsum[SCAN_BLK / 32];
    int i = blockIdx.x * SCAN_BLK + threadIdx.x;
    int v = (i < NN) ? g_hist[i] : 0;
#pragma unroll
    for (int d = 16; d > 0; d >>= 1) v += __shfl_down_sync(0xffffffffu, v, d);
    if ((threadIdx.x & 31) == 0) wsum[threadIdx.x >> 5] = v;
    __syncthreads();
    if (threadIdx.x < SCAN_BLK / 32) {
        int s = wsum[threadIdx.x];
#pragma unroll
        for (int d = SCAN_BLK / 64; d > 0; d >>= 1)
            s += __shfl_down_sync(0xffu, s, d);
        if (threadIdx.x == 0) g_bsum[blockIdx.x] = s;
    }
}

__global__ __launch_bounds__(256) void scan_bsum_kernel()
{
    __shared__ int sh[256];
    int t = threadIdx.x;
    int v = (t < SCAN_NB) ? g_bsum[t] : 0;
    sh[t] = v;
    __syncthreads();
#pragma unroll
    for (int d = 1; d < 256; d <<= 1) {
        int u = (t >= d) ? sh[t - d] : 0;
        __syncthreads();
        sh[t] += u;
        __syncthreads();
    }
    if (t < SCAN_NB) g_bpre[t] = sh[t] - v;
}

__global__ __launch_bounds__(SCAN_BLK) void scan_final_kernel()
{
    __shared__ int wpre[SCAN_BLK / 32];
    int i    = blockIdx.x * SCAN_BLK + threadIdx.x;
    int lane = threadIdx.x & 31;
    int wid  = threadIdx.x >> 5;
    int v    = (i < NN) ? g_hist[i] : 0;

    int inc = v;
#pragma unroll
    for (int d = 1; d < 32; d <<= 1) {
        int u = __shfl_up_sync(0xffffffffu, inc, d);
        if (lane >= d) inc += u;
    }
    if (lane == 31) wpre[wid] = inc;
    __syncthreads();
    if (threadIdx.x < SCAN_BLK / 32) {
        int s = wpre[threadIdx.x];
#pragma unroll
        for (int d = 1; d < SCAN_BLK / 32; d <<= 1) {
            int u = __shfl_up_sync(0xffu, s, d);
            if ((int)threadIdx.x >= d) s += u;
        }
        wpre[threadIdx.x] = s;
    }
    __syncthreads();

    int warp_prefix = (wid == 0) ? 0 : wpre[wid - 1];
    int exc = g_bpre[blockIdx.x] + warp_prefix + (inc - v);
    if (i < NN) {
        g_off[i]    = exc;
        g_cursor[i] = exc;
    }
}

__global__ void reorder_kernel(const int* __restrict__ erow,
                               const int* __restrict__ ecol,
                               const float* __restrict__ ew)
{
    int e = blockIdx.x * blockDim.x + threadIdx.x;
    if (e >= NE) return;
    int r   = erow[e];
    int pos = atomicAdd(&g_cursor[r], 1);
    g_edge[pos] = make_int2(ecol[e], __float_as_int(ew[e]));
}

// ---------------------------------------------------------------------------
// Gather-side reduction (unchanged from R3)
// ---------------------------------------------------------------------------
__global__ __launch_bounds__(256) void gather_kernel(
    float* __restrict__ out, const float* __restrict__ b)
{
    const int warp = (blockIdx.x * blockDim.x + threadIdx.x) >> 5;
    const int lane = threadIdx.x & 31;
    if (warp >= NN) return;

    const int start = g_off[warp];
    const int end   = start + g_hist[warp];

    const float4* y4 = reinterpret_cast<const float4*>(g_y);
    float4 acc = *reinterpret_cast<const float4*>(&b[lane * 4]);

    for (int base = start; base < end; base += 32) {
        int n = min(32, end - base);
        int2 e = make_int2(0, 0);
        if (lane < n) e = g_edge[base + lane];
#pragma unroll 4
        for (int jj = 0; jj < n; jj++) {
            int   cc = __shfl_sync(0xffffffffu, e.x, jj);
            float ww = __int_as_float(__shfl_sync(0xffffffffu, e.y, jj));
            float4 v = y4[cc * 32 + lane];
            acc.x += ww * v.x;
            acc.y += ww * v.y;
            acc.z += ww * v.z;
            acc.w += ww * v.w;
        }
    }

    reinterpret_cast<float4*>(out)[warp * 32 + lane] = acc;
}

// ---------------------------------------------------------------------------
extern "C" void kernel_launch(void* const* d_in, const int* in_sizes, int n_in,
                              void* d_out, int out_size)
{
    const float* x    = (const float*)d_in[0];
    const int*   erow = (const int*)  d_in[1];
    const int*   ecol = (const int*)  d_in[2];
    const float* ew   = (const float*)d_in[3];
    const float* W    = (const float*)d_in[4];
    const float* b    = (const float*)d_in[5];
    float*       out  = (float*)d_out;

    cudaFuncSetAttribute(transform_mma_kernel,
                         cudaFuncAttributeMaxDynamicSharedMemorySize, SM_DYN);

    zero_hist_kernel<<<(NN + 255) / 256, 256>>>();
    count_kernel<<<(NE + 255) / 256, 256>>>(erow);
    transform_mma_kernel<<<TBLK, 256, SM_DYN>>>(x, W);
    scan_partials_kernel<<<SCAN_NB, SCAN_BLK>>>();
    scan_bsum_kernel<<<1, 256>>>();
    scan_final_kernel<<<SCAN_NB, SCAN_BLK>>>();
    reorder_kernel<<<(NE + 255) / 256, 256>>>(erow, ecol, ew);
    gather_kernel<<<(NN * 32 + 255) / 256, 256>>>(out, b);
}